// round 2
// baseline (speedup 1.0000x reference)
#include <cuda_runtime.h>
#include <math_constants.h>

// MaxPlusDense: out[b,u] = max( max_i (x[b,i] - kernel[i,u]), bias[u] )
// B=256, D=1024, U=1024, fp32.
// Issue-bound problem (FSUB on fma pipe + FMNMX on alu pipe, 1/cyc/SMSP combined).

#define B_DIM 256
#define D_DIM 1024
#define U_DIM 1024

#define BM 32
#define BN 64
#define BK 32
#define NT 256

__global__ __launch_bounds__(NT, 1) void maxplus_kernel(
    const float* __restrict__ X,     // (B, D)
    const float* __restrict__ W,     // (D, U)
    const float* __restrict__ bias,  // (U,)
    float* __restrict__ out)         // (B, U)
{
    __shared__ float xs[BK][BM + 2];   // x tile transposed: xs[k][m], +2 pad kills bank conflicts
    __shared__ float ks[BK][BN];       // kernel tile: ks[k][n]

    const int tid = threadIdx.x;
    const int bm = blockIdx.y * BM;
    const int bn = blockIdx.x * BN;

    // each thread computes a 2(m) x 4(n) microtile
    const int tm = (tid & 15) * 2;     // 0..30
    const int tn = (tid >> 4) * 4;     // 0..60

    // global->smem load mapping
    const int xr = tid >> 3;           // 0..31 : m within x tile
    const int xc = (tid & 7) * 4;      // 0..28 : k within x tile (float4 along D)
    const int kr = tid >> 4;           // 0..15 : k within kernel tile
    const int kc = (tid & 15) * 4;     // 0..60 : n within kernel tile (float4 along U)

    const float* xg  = X + (bm + xr) * D_DIM + xc;
    const float* kg0 = W + kr * U_DIM + bn + kc;
    const float* kg1 = W + (kr + 16) * U_DIM + bn + kc;

    float acc[2][4];
#pragma unroll
    for (int i = 0; i < 2; i++)
#pragma unroll
        for (int j = 0; j < 4; j++) acc[i][j] = -CUDART_INF_F;

    // prologue: stage first tiles in registers
    float4 xv  = *(const float4*)(xg);
    float4 kv0 = *(const float4*)(kg0);
    float4 kv1 = *(const float4*)(kg1);

    for (int k0 = 0; k0 < D_DIM; k0 += BK) {
        // commit staged regs to smem
        xs[xc + 0][xr] = xv.x;
        xs[xc + 1][xr] = xv.y;
        xs[xc + 2][xr] = xv.z;
        xs[xc + 3][xr] = xv.w;
        *(float4*)&ks[kr][kc]      = kv0;
        *(float4*)&ks[kr + 16][kc] = kv1;
        __syncthreads();

        // prefetch next tiles (L2-resident) while computing this one
        if (k0 + BK < D_DIM) {
            xv  = *(const float4*)(xg + k0 + BK);
            kv0 = *(const float4*)(kg0 + (size_t)(k0 + BK) * U_DIM);
            kv1 = *(const float4*)(kg1 + (size_t)(k0 + BK) * U_DIM);
        }

#pragma unroll
        for (int kk = 0; kk < BK; kk++) {
            float2 a = *(const float2*)&xs[kk][tm];
            float4 b = *(const float4*)&ks[kk][tn];
            acc[0][0] = fmaxf(acc[0][0], a.x - b.x);
            acc[0][1] = fmaxf(acc[0][1], a.x - b.y);
            acc[0][2] = fmaxf(acc[0][2], a.x - b.z);
            acc[0][3] = fmaxf(acc[0][3], a.x - b.w);
            acc[1][0] = fmaxf(acc[1][0], a.y - b.x);
            acc[1][1] = fmaxf(acc[1][1], a.y - b.y);
            acc[1][2] = fmaxf(acc[1][2], a.y - b.z);
            acc[1][3] = fmaxf(acc[1][3], a.y - b.w);
        }
        __syncthreads();
    }

    // epilogue: elementwise max with bias, vectorized store
    float4 bv = *(const float4*)&bias[bn + tn];
#pragma unroll
    for (int i = 0; i < 2; i++) {
        float4 o;
        o.x = fmaxf(acc[i][0], bv.x);
        o.y = fmaxf(acc[i][1], bv.y);
        o.z = fmaxf(acc[i][2], bv.z);
        o.w = fmaxf(acc[i][3], bv.w);
        *(float4*)&out[(size_t)(bm + tm + i) * U_DIM + bn + tn] = o;
    }
}

extern "C" void kernel_launch(void* const* d_in, const int* in_sizes, int n_in,
                              void* d_out, int out_size)
{
    const float* x      = (const float*)d_in[0];   // (256, 1024)
    const float* kernel = (const float*)d_in[1];   // (1024, 1024)
    const float* bias   = (const float*)d_in[2];   // (1024,)
    float* out          = (float*)d_out;           // (256, 1024)

    dim3 grid(U_DIM / BN, B_DIM / BM);   // (16, 8) = 128 CTAs
    dim3 block(NT);
    maxplus_kernel<<<grid, block>>>(x, kernel, bias, out);
}